// round 8
// baseline (speedup 1.0000x reference)
#include <cuda_runtime.h>
#include <cuda_bf16.h>
#include <cstdint>
#include <math.h>

// ---------------- Problem constants ----------------
#define D_MODEL   1024
#define HEADDIM   64
#define D_STATE   128
#define D_INNER   2048
#define NHEADS    32
#define CONV_DIM  2304           // D_INNER + 2*D_STATE
#define D_IN_PROJ 4384           // 2*D_INNER + 2*D_STATE + NHEADS
#define BATCH     4
#define SEQ       2048
#define ROWS      (BATCH*SEQ)    // 8192
#define EPSV      1e-5f

#define NCHUNK    16
#define LCHUNK    (SEQ/NCHUNK)   // 128
#define NBH       (BATCH*NHEADS) // 128
#define STATE_SZ  (HEADDIM*D_STATE)  // 8192

typedef unsigned long long ull;

// ---------------- Scratch (static device memory; no allocations) ----------------
__device__ float g_zxb[(size_t)ROWS * D_IN_PROJ];   // in-proj output
__device__ float g_xbc[(size_t)ROWS * CONV_DIM];    // conv+silu output
__device__ float g_dt [NBH*SEQ];
__device__ float g_dA [NBH*SEQ];
__device__ float g_yb [(size_t)ROWS * D_INNER];     // scan output + D*x

// chunked-scan intermediates
__device__ float g_st   [(size_t)NBH * NCHUNK * STATE_SZ];  // per-chunk local final state
__device__ float g_hini [(size_t)NBH * NCHUNK * STATE_SZ];  // per-chunk initial state
__device__ float g_cum  [NBH * NCHUNK];                     // per-chunk prod(dA)

// bf16 split operands for tensor-core GEMMs
__device__ __nv_bfloat16 g_qh [(size_t)ROWS * D_MODEL];
__device__ __nv_bfloat16 g_ql [(size_t)ROWS * D_MODEL];
__device__ __nv_bfloat16 g_w1h[(size_t)D_IN_PROJ * D_MODEL];
__device__ __nv_bfloat16 g_w1l[(size_t)D_IN_PROJ * D_MODEL];
__device__ __nv_bfloat16 g_ynh[(size_t)ROWS * D_INNER];
__device__ __nv_bfloat16 g_ynl[(size_t)ROWS * D_INNER];
__device__ __nv_bfloat16 g_w2h[(size_t)D_MODEL * D_INNER];
__device__ __nv_bfloat16 g_w2l[(size_t)D_MODEL * D_INNER];

// ---------------- f32x2 packed helpers ----------------
__device__ __forceinline__ ull pack2(float lo, float hi) {
    ull r; asm("mov.b64 %0, {%1,%2};" : "=l"(r) : "f"(lo), "f"(hi)); return r;
}
__device__ __forceinline__ void unpack2(ull v, float& lo, float& hi) {
    asm("mov.b64 {%0,%1}, %2;" : "=f"(lo), "=f"(hi) : "l"(v));
}
__device__ __forceinline__ void fma2(ull& d, ull a, ull b) {
    asm("fma.rn.f32x2 %0, %1, %2, %0;" : "+l"(d) : "l"(a), "l"(b));
}
__device__ __forceinline__ ull mul2(ull a, ull b) {
    ull r; asm("mul.rn.f32x2 %0, %1, %2;" : "=l"(r) : "l"(a), "l"(b)); return r;
}

// ---------------- cp.async helpers ----------------
__device__ __forceinline__ void cp16(unsigned s, const void* g) {
    asm volatile("cp.async.ca.shared.global [%0], [%1], 16;" :: "r"(s), "l"(g));
}
__device__ __forceinline__ void cp16z(unsigned s, const void* g, unsigned sz) {
    asm volatile("cp.async.ca.shared.global [%0], [%1], 16, %2;" :: "r"(s), "l"(g), "r"(sz));
}
__device__ __forceinline__ void cp_commit() { asm volatile("cp.async.commit_group;"); }
template<int N> __device__ __forceinline__ void cp_wait() {
    asm volatile("cp.async.wait_group %0;" :: "n"(N));
}
__device__ __forceinline__ unsigned smem_u32(const void* p) {
    return (unsigned)__cvta_generic_to_shared(p);
}

// ---------------- mma.sync + ldmatrix ----------------
#define LDSM4(r, addr) \
    asm volatile("ldmatrix.sync.aligned.m8n8.x4.shared.b16 {%0,%1,%2,%3}, [%4];" \
        : "=r"((r)[0]), "=r"((r)[1]), "=r"((r)[2]), "=r"((r)[3]) : "r"(addr))

#define MMA16816(d, a, b) \
    asm volatile("mma.sync.aligned.m16n8k16.row.col.f32.bf16.bf16.f32 " \
        "{%0,%1,%2,%3}, {%4,%5,%6,%7}, {%8,%9}, {%0,%1,%2,%3};" \
        : "+f"((d)[0]), "+f"((d)[1]), "+f"((d)[2]), "+f"((d)[3]) \
        : "r"((a)[0]), "r"((a)[1]), "r"((a)[2]), "r"((a)[3]), \
          "r"((b)[0]), "r"((b)[1]))

// =====================================================================
// Split-bf16 HMMA GEMM (NT): C = Ah*Bh + Al*Bh + Ah*Bl (fp32 accum)
// =====================================================================
#define GEMM_STG   98304
#define GEMM_SMEM  (2*GEMM_STG)

__global__ void __launch_bounds__(256, 1)
gemm_mma(const __nv_bfloat16* __restrict__ A_h, const __nv_bfloat16* __restrict__ A_l,
         const __nv_bfloat16* __restrict__ B_h, const __nv_bfloat16* __restrict__ B_l,
         float* __restrict__ C, int M, int N, int K)
{
    extern __shared__ __align__(1024) char sm[];
    const unsigned base = smem_u32(sm);
    const int tid  = threadIdx.x;
    const int lane = tid & 31;
    const int wid  = tid >> 5;
    const int wm   = wid >> 2;
    const int wn   = wid & 3;
    const int m0   = blockIdx.y * 128;
    const int n0   = blockIdx.x * 256;

    float acc[4][8][4];
#pragma unroll
    for (int t = 0; t < 4; t++)
#pragma unroll
        for (int u = 0; u < 8; u++)
#pragma unroll
            for (int v = 0; v < 4; v++) acc[t][u][v] = 0.f;

    auto load_stage = [&](int s, unsigned stg) {
        const int k0 = s * 64;
#pragma unroll
        for (int i = 0; i < 4; i++) {
            const int ch = tid + i * 256;
            const int row = ch >> 3, c = ch & 7;
            const unsigned off = (unsigned)(row * 128) + ((unsigned)(c ^ (row & 7)) << 4);
            const size_t g = (size_t)(m0 + row) * K + k0 + c * 8;
            cp16(stg + off,         A_h + g);
            cp16(stg + 16384 + off, A_l + g);
        }
#pragma unroll
        for (int i = 0; i < 8; i++) {
            const int ch = tid + i * 256;
            const int row = ch >> 3, c = ch & 7;
            const unsigned off = (unsigned)(row * 128) + ((unsigned)(c ^ (row & 7)) << 4);
            const int gr = n0 + row;
            const unsigned sz = (gr < N) ? 16u : 0u;
            const int grc = (gr < N) ? gr : 0;
            const size_t g = (size_t)grc * K + k0 + c * 8;
            cp16z(stg + 32768 + off, B_h + g, sz);
            cp16z(stg + 65536 + off, B_l + g, sz);
        }
        cp_commit();
    };

    const int S = K / 64;
    load_stage(0, base);

    for (int s = 0; s < S; s++) {
        const unsigned stg = base + (unsigned)(s & 1) * GEMM_STG;
        if (s + 1 < S) {
            load_stage(s + 1, base + (unsigned)((s + 1) & 1) * GEMM_STG);
            cp_wait<1>();
        } else {
            cp_wait<0>();
        }
        __syncthreads();

        const unsigned stgA  = stg;
        const unsigned stgAl = stg + 16384;
        const unsigned stgB  = stg + 32768;
        const unsigned stgBl = stg + 65536;

#pragma unroll
        for (int ks = 0; ks < 4; ks++) {
            unsigned ah[4][4], al[4][4], bb[8][2];
            const unsigned akoff = ((unsigned)((ks * 2 + (lane >> 4)) ^ (lane & 7))) << 4;
#pragma unroll
            for (int t = 0; t < 4; t++) {
                const unsigned ro = (unsigned)((wm * 64 + t * 16 + (lane & 15)) * 128);
                LDSM4(ah[t], stgA  + ro + akoff);
                LDSM4(al[t], stgAl + ro + akoff);
            }
            const unsigned bkoff = ((unsigned)((ks * 2 + ((lane >> 3) & 1)) ^ (lane & 7))) << 4;
#pragma unroll
            for (int p = 0; p < 4; p++) {
                const unsigned ro = (unsigned)((wn * 64 + p * 16 + (lane & 7) + ((lane & 16) >> 1)) * 128);
                unsigned r[4];
                LDSM4(r, stgB + ro + bkoff);
                bb[2*p][0] = r[0]; bb[2*p][1] = r[1];
                bb[2*p+1][0] = r[2]; bb[2*p+1][1] = r[3];
            }
#pragma unroll
            for (int t = 0; t < 4; t++)
#pragma unroll
                for (int u = 0; u < 8; u++) {
                    MMA16816(acc[t][u], ah[t], bb[u]);
                    MMA16816(acc[t][u], al[t], bb[u]);
                }
#pragma unroll
            for (int p = 0; p < 4; p++) {
                const unsigned ro = (unsigned)((wn * 64 + p * 16 + (lane & 7) + ((lane & 16) >> 1)) * 128);
                unsigned r[4];
                LDSM4(r, stgBl + ro + bkoff);
                bb[2*p][0] = r[0]; bb[2*p][1] = r[1];
                bb[2*p+1][0] = r[2]; bb[2*p+1][1] = r[3];
            }
#pragma unroll
            for (int t = 0; t < 4; t++)
#pragma unroll
                for (int u = 0; u < 8; u++)
                    MMA16816(acc[t][u], ah[t], bb[u]);
        }
        __syncthreads();
    }

#pragma unroll
    for (int t = 0; t < 4; t++) {
        const int row = m0 + wm * 64 + t * 16 + (lane >> 2);
#pragma unroll
        for (int u = 0; u < 8; u++) {
            const int col = n0 + wn * 64 + u * 8 + (lane & 3) * 2;
            if (col < N) {
                *(float2*)(C + (size_t)row * N + col)       = make_float2(acc[t][u][0], acc[t][u][1]);
                *(float2*)(C + (size_t)(row + 8) * N + col) = make_float2(acc[t][u][2], acc[t][u][3]);
            }
        }
    }
}

// =====================================================================
// fp32 -> (bf16 hi, bf16 lo) split conversion
// =====================================================================
__global__ void __launch_bounds__(256) cvt_pair(const float* __restrict__ src,
                                                __nv_bfloat16* __restrict__ h,
                                                __nv_bfloat16* __restrict__ l, int n4)
{
    const int i = blockIdx.x * 256 + threadIdx.x;
    if (i >= n4) return;
    const float4 v = ((const float4*)src)[i];
    __nv_bfloat16 h0 = __float2bfloat16(v.x), h1 = __float2bfloat16(v.y),
                  h2 = __float2bfloat16(v.z), h3 = __float2bfloat16(v.w);
    __nv_bfloat16 l0 = __float2bfloat16(v.x - __bfloat162float(h0));
    __nv_bfloat16 l1 = __float2bfloat16(v.y - __bfloat162float(h1));
    __nv_bfloat16 l2 = __float2bfloat16(v.z - __bfloat162float(h2));
    __nv_bfloat16 l3 = __float2bfloat16(v.w - __bfloat162float(h3));
    ushort4 hv = make_ushort4(*(unsigned short*)&h0, *(unsigned short*)&h1,
                              *(unsigned short*)&h2, *(unsigned short*)&h3);
    ushort4 lv = make_ushort4(*(unsigned short*)&l0, *(unsigned short*)&l1,
                              *(unsigned short*)&l2, *(unsigned short*)&l3);
    ((ushort4*)h)[i] = hv;
    ((ushort4*)l)[i] = lv;
}

// =====================================================================
// Depthwise causal conv (width 4) + SiLU
// =====================================================================
__global__ void __launch_bounds__(256) conv_silu_kernel(const float* __restrict__ conv_w,
                                                        const float* __restrict__ conv_b)
{
    const int c  = blockIdx.x * 256 + threadIdx.x;
    const int l0 = blockIdx.y * 128;
    const int b  = blockIdx.z;

    const float w0 = conv_w[c*4+0], w1 = conv_w[c*4+1],
                w2 = conv_w[c*4+2], w3 = conv_w[c*4+3];
    const float bias = conv_b[c];

    const float* src = g_zxb + (size_t)(b*SEQ) * D_IN_PROJ + D_INNER + c;
    float*       dst = g_xbc + (size_t)(b*SEQ) * CONV_DIM + c;

    float xm3 = (l0-3 >= 0) ? src[(size_t)(l0-3) * D_IN_PROJ] : 0.f;
    float xm2 = (l0-2 >= 0) ? src[(size_t)(l0-2) * D_IN_PROJ] : 0.f;
    float xm1 = (l0-1 >= 0) ? src[(size_t)(l0-1) * D_IN_PROJ] : 0.f;

    for (int l = l0; l < l0 + 128; l++) {
        const float xc = src[(size_t)l * D_IN_PROJ];
        float v = bias + w0*xm3 + w1*xm2 + w2*xm1 + w3*xc;
        v = v / (1.f + expf(-v));
        dst[(size_t)l * CONV_DIM] = v;
        xm3 = xm2; xm2 = xm1; xm1 = xc;
    }
}

// =====================================================================
// dt = softplus(raw + dt_bias); dA = exp(-exp(A_log)*dt)   layout [bh][l]
// =====================================================================
__global__ void __launch_bounds__(256) dt_kernel(const float* __restrict__ dt_bias,
                                                 const float* __restrict__ A_log)
{
    const int idx = blockIdx.x * 256 + threadIdx.x;
    if (idx >= NBH*SEQ) return;
    const int l = idx & (SEQ-1);
    const int h = (idx >> 11) & (NHEADS-1);
    const int b = idx >> 16;
    const float raw = g_zxb[(size_t)(b*SEQ + l) * D_IN_PROJ + (D_IN_PROJ - NHEADS) + h]
                      + dt_bias[h];
    const float sp = (raw > 20.f) ? raw : log1pf(expf(raw));
    const float Ahv = -expf(A_log[h]);
    g_dt[idx] = sp;
    g_dA[idx] = expf(Ahv * sp);
}

// =====================================================================
// Phase 1: per-chunk local state.  grid (NCHUNK, NBH), 256 threads.
// h_local over 128 steps from zero; writes S_local + prod(dA).
// =====================================================================
__global__ void __launch_bounds__(256) chunk_state_kernel()
{
    const int ck  = blockIdx.x;
    const int bh  = blockIdx.y;
    const int b   = bh >> 5;
    const int tid = threadIdx.x;
    const int p   = tid >> 2;
    const int q   = tid & 3;
    const int t0g = ck * LCHUNK;

    __shared__ __align__(16) float sB[2][8][D_STATE];
    __shared__ __align__(16) float sX[2][8][HEADDIM];
    __shared__ float sDt[LCHUNK];
    __shared__ float sDA[LCHUNK];

    const float* dtp = g_dt + (size_t)bh * SEQ + t0g;
    const float* dap = g_dA + (size_t)bh * SEQ + t0g;
    if (tid < LCHUNK) { sDt[tid] = dtp[tid]; sDA[tid] = dap[tid]; }

    ull h2[16];
#pragma unroll
    for (int i = 0; i < 16; i++) h2[i] = 0ull;

    auto preload = [&](int blk, int buf) {
        const int t0 = t0g + blk * 8;
        {
            const int s = tid >> 5, seg = tid & 31;
            const float* rowp = g_xbc + (size_t)(b*SEQ + t0 + s) * CONV_DIM;
            cp16(smem_u32(&sB[buf][s][seg*4]), rowp + D_INNER + seg*4);
        }
        if (tid < 128) {
            const int s = tid >> 4, seg = tid & 15;
            const int hh = bh & (NHEADS-1);
            const float* rowp = g_xbc + (size_t)(b*SEQ + t0 + s) * CONV_DIM;
            cp16(smem_u32(&sX[buf][s][seg*4]), rowp + hh*HEADDIM + seg*4);
        }
        cp_commit();
    };

    const int NBLK = LCHUNK / 8;   // 16
    int buf = 0;
    preload(0, 0);
    __syncthreads();   // also covers sDt/sDA

    if (tid == 0) {
        float cum = 1.f;
#pragma unroll 8
        for (int i = 0; i < LCHUNK; i++) cum *= sDA[i];
        g_cum[bh * NCHUNK + ck] = cum;
    }

    for (int blk = 0; blk < NBLK; blk++) {
        if (blk + 1 < NBLK) { preload(blk + 1, buf ^ 1); cp_wait<1>(); }
        else                { cp_wait<0>(); }
        __syncthreads();

#pragma unroll
        for (int s = 0; s < 8; s++) {
            const int t = blk*8 + s;
            const float dtv = sDt[t];
            const float dav = sDA[t];
            const float xv  = sX[buf][s][p];
            const float coef = dtv * xv;
            const ull dA2 = pack2(dav, dav);
            const ull cf2 = pack2(coef, coef);
            const ull* Bp = (const ull*)&sB[buf][s][q*32];
#pragma unroll
            for (int i = 0; i < 16; i++) {
                ull t2 = mul2(cf2, Bp[i]);
                fma2(t2, h2[i], dA2);
                h2[i] = t2;
            }
        }
        __syncthreads();
        buf ^= 1;
    }

    // write S_local: layout (bh, ck, p, n)
    ull* dst = (ull*)(g_st + ((size_t)(bh * NCHUNK + ck) * HEADDIM + p) * D_STATE + q * 32);
#pragma unroll
    for (int i = 0; i < 16; i++) dst[i] = h2[i];
}

// =====================================================================
// Phase 2: combine across chunks.  grid NBH, 256 threads.
// h_init_0 = 0;  h_init_c = cum_{c-1} * h_init_{c-1} + S_{c-1}
// =====================================================================
__global__ void __launch_bounds__(256) chunk_combine_kernel()
{
    const int bh  = blockIdx.x;
    const int tid = threadIdx.x;
    const size_t off = tid * 32;      // 32 floats per thread of 8192

    float4 h[8];
#pragma unroll
    for (int i = 0; i < 8; i++) h[i] = make_float4(0.f, 0.f, 0.f, 0.f);

    for (int ck = 0; ck < NCHUNK; ck++) {
        float4* hi = (float4*)(g_hini + (size_t)(bh * NCHUNK + ck) * STATE_SZ + off);
#pragma unroll
        for (int i = 0; i < 8; i++) hi[i] = h[i];
        if (ck < NCHUNK - 1) {
            const float a = g_cum[bh * NCHUNK + ck];
            const float4* s = (const float4*)(g_st + (size_t)(bh * NCHUNK + ck) * STATE_SZ + off);
#pragma unroll
            for (int i = 0; i < 8; i++) {
                float4 sv = s[i];
                h[i].x = a * h[i].x + sv.x;
                h[i].y = a * h[i].y + sv.y;
                h[i].z = a * h[i].z + sv.z;
                h[i].w = a * h[i].w + sv.w;
            }
        }
    }
}

// =====================================================================
// Phase 3: per-chunk scan with outputs.  grid (NCHUNK, NBH), 256 threads.
// =====================================================================
__global__ void __launch_bounds__(256) chunk_scan_kernel(const float* __restrict__ Dvec)
{
    const int ck  = blockIdx.x;
    const int bh  = blockIdx.y;
    const int b   = bh >> 5;
    const int hh  = bh & (NHEADS-1);
    const int tid = threadIdx.x;
    const int p   = tid >> 2;
    const int q   = tid & 3;
    const int t0g = ck * LCHUNK;

    __shared__ __align__(16) float sB[2][8][D_STATE];
    __shared__ __align__(16) float sC[2][8][D_STATE];
    __shared__ __align__(16) float sX[2][8][HEADDIM];
    __shared__ float sDt[LCHUNK];
    __shared__ float sDA[LCHUNK];

    const float* dtp = g_dt + (size_t)bh * SEQ + t0g;
    const float* dap = g_dA + (size_t)bh * SEQ + t0g;
    if (tid < LCHUNK) { sDt[tid] = dtp[tid]; sDA[tid] = dap[tid]; }

    const float Dv = Dvec[hh];

    // initial state for this chunk
    ull h2[16];
    {
        const ull* src = (const ull*)(g_hini + ((size_t)(bh * NCHUNK + ck) * HEADDIM + p) * D_STATE + q * 32);
#pragma unroll
        for (int i = 0; i < 16; i++) h2[i] = src[i];
    }

    auto preload = [&](int blk, int buf) {
        const int t0 = t0g + blk * 8;
        {
            const int s = tid >> 5, seg = tid & 31;
            const float* rowp = g_xbc + (size_t)(b*SEQ + t0 + s) * CONV_DIM;
            cp16(smem_u32(&sB[buf][s][seg*4]), rowp + D_INNER + seg*4);
            cp16(smem_u32(&sC[buf][s][seg*4]), rowp + D_INNER + D_STATE + seg*4);
        }
        if (tid < 128) {
            const int s = tid >> 4, seg = tid & 15;
            const float* rowp = g_xbc + (size_t)(b*SEQ + t0 + s) * CONV_DIM;
            cp16(smem_u32(&sX[buf][s][seg*4]), rowp + hh*HEADDIM + seg*4);
        }
        cp_commit();
    };

    const int NBLK = LCHUNK / 8;   // 16
    int buf = 0;
    preload(0, 0);

    for (int blk = 0; blk < NBLK; blk++) {
        if (blk + 1 < NBLK) { preload(blk + 1, buf ^ 1); cp_wait<1>(); }
        else                { cp_wait<0>(); }
        __syncthreads();

#pragma unroll
        for (int s = 0; s < 8; s++) {
            const int t = blk*8 + s;
            const float dtv = sDt[t];
            const float dav = sDA[t];
            const float xv  = sX[buf][s][p];
            const float coef = dtv * xv;
            const ull dA2 = pack2(dav, dav);
            const ull cf2 = pack2(coef, coef);
            const ull* Bp = (const ull*)&sB[buf][s][q*32];
            const ull* Cp = (const ull*)&sC[buf][s][q*32];
            ull yacc = 0ull;
#pragma unroll
            for (int i = 0; i < 16; i++) {
                ull t2 = mul2(cf2, Bp[i]);
                fma2(t2, h2[i], dA2);
                h2[i] = t2;
                fma2(yacc, t2, Cp[i]);
            }
            float ylo, yhi; unpack2(yacc, ylo, yhi);
            float yv = ylo + yhi;
            yv += __shfl_xor_sync(0xffffffffu, yv, 1);
            yv += __shfl_xor_sync(0xffffffffu, yv, 2);
            if (q == 0) {
                g_yb[((size_t)(b*SEQ + t0g + t) * NHEADS + hh) * HEADDIM + p] = yv + Dv * xv;
            }
        }
        __syncthreads();
        buf ^= 1;
    }
}

// =====================================================================
// y = yb * silu(z); rmsnorm; write bf16 hi/lo split (GEMM2 A operand)
// =====================================================================
__global__ void __launch_bounds__(256) gate_norm_kernel(const float* __restrict__ norm_w)
{
    const int row = blockIdx.x;
    const int tid = threadIdx.x;
    const float* yb = g_yb + (size_t)row * D_INNER;
    const float* zr = g_zxb + (size_t)row * D_IN_PROJ;

    float v[8];
    float ss = 0.f;
#pragma unroll
    for (int j = 0; j < 8; j++) {
        const int idx = tid + j*256;
        const float z = zr[idx];
        const float sg = z / (1.f + expf(-z));
        const float val = yb[idx] * sg;
        v[j] = val;
        ss += val * val;
    }
#pragma unroll
    for (int o = 16; o > 0; o >>= 1) ss += __shfl_xor_sync(0xffffffffu, ss, o);

    __shared__ float red[8];
    __shared__ float sscale;
    if ((tid & 31) == 0) red[tid >> 5] = ss;
    __syncthreads();
    if (tid == 0) {
        float tot = 0.f;
#pragma unroll
        for (int i = 0; i < 8; i++) tot += red[i];
        sscale = rsqrtf(tot / (float)D_INNER + EPSV);
    }
    __syncthreads();
    const float scale = sscale;

    __nv_bfloat16* oh = g_ynh + (size_t)row * D_INNER;
    __nv_bfloat16* ol = g_ynl + (size_t)row * D_INNER;
#pragma unroll
    for (int j = 0; j < 8; j++) {
        const int idx = tid + j*256;
        const float y = v[j] * scale * norm_w[idx];
        const __nv_bfloat16 hi = __float2bfloat16(y);
        oh[idx] = hi;
        ol[idx] = __float2bfloat16(y - __bfloat162float(hi));
    }
}

// =====================================================================
// Launch
// inputs: 0 query, 1 key, 2 value, 3 in_proj_w, 4 conv_w, 5 conv_b,
//         6 dt_bias, 7 A_log, 8 D, 9 norm_w, 10 out_proj_w
// =====================================================================
extern "C" void kernel_launch(void* const* d_in, const int* in_sizes, int n_in,
                              void* d_out, int out_size)
{
    const float* q          = (const float*)d_in[0];
    const float* in_proj_w  = (const float*)d_in[3];
    const float* conv_w     = (const float*)d_in[4];
    const float* conv_b     = (const float*)d_in[5];
    const float* dt_bias    = (const float*)d_in[6];
    const float* A_log      = (const float*)d_in[7];
    const float* Dvec       = (const float*)d_in[8];
    const float* norm_w     = (const float*)d_in[9];
    const float* out_proj_w = (const float*)d_in[10];
    float* out              = (float*)d_out;

    float* zxb; cudaGetSymbolAddress((void**)&zxb, g_zxb);
    __nv_bfloat16 *qh, *ql, *w1h, *w1l, *ynh, *ynl, *w2h, *w2l;
    cudaGetSymbolAddress((void**)&qh,  g_qh);
    cudaGetSymbolAddress((void**)&ql,  g_ql);
    cudaGetSymbolAddress((void**)&w1h, g_w1h);
    cudaGetSymbolAddress((void**)&w1l, g_w1l);
    cudaGetSymbolAddress((void**)&ynh, g_ynh);
    cudaGetSymbolAddress((void**)&ynl, g_ynl);
    cudaGetSymbolAddress((void**)&w2h, g_w2h);
    cudaGetSymbolAddress((void**)&w2l, g_w2l);

    cudaFuncSetAttribute(gemm_mma, cudaFuncAttributeMaxDynamicSharedMemorySize, GEMM_SMEM);

    // 0) split-convert GEMM operands
    {
        const int nq = ROWS * D_MODEL / 4;
        cvt_pair<<<(nq + 255)/256, 256>>>(q, qh, ql, nq);
        const int nw1 = D_IN_PROJ * D_MODEL / 4;
        cvt_pair<<<(nw1 + 255)/256, 256>>>(in_proj_w, w1h, w1l, nw1);
        const int nw2 = D_MODEL * D_INNER / 4;
        cvt_pair<<<(nw2 + 255)/256, 256>>>(out_proj_w, w2h, w2l, nw2);
    }

    // 1) zxbcdt = q @ in_proj_w^T
    gemm_mma<<<dim3((D_IN_PROJ + 255)/256, ROWS/128), 256, GEMM_SMEM>>>(
        qh, ql, w1h, w1l, zxb, ROWS, D_IN_PROJ, D_MODEL);

    // 2) causal conv4 + SiLU
    conv_silu_kernel<<<dim3(CONV_DIM/256, SEQ/128, BATCH), 256>>>(conv_w, conv_b);

    // 3) dt / dA
    dt_kernel<<<(NBH*SEQ + 255)/256, 256>>>(dt_bias, A_log);

    // 4) chunked selective scan (3 phases)
    chunk_state_kernel<<<dim3(NCHUNK, NBH), 256>>>();
    chunk_combine_kernel<<<NBH, 256>>>();
    chunk_scan_kernel<<<dim3(NCHUNK, NBH), 256>>>(Dvec);

    // 5) gate + RMSNorm (emits bf16 hi/lo)
    gate_norm_kernel<<<ROWS, 256>>>(norm_w);

    // 6) out = yn @ out_proj_w^T
    gemm_mma<<<dim3(D_MODEL/256, ROWS/128), 256, GEMM_SMEM>>>(
        ynh, ynl, w2h, w2l, out, ROWS, D_MODEL, D_INNER);
}

// round 10
// speedup vs baseline: 2.1116x; 2.1116x over previous
#include <cuda_runtime.h>
#include <cuda_bf16.h>
#include <cstdint>
#include <math.h>

// ---------------- Problem constants ----------------
#define D_MODEL   1024
#define HEADDIM   64
#define D_STATE   128
#define D_INNER   2048
#define NHEADS    32
#define CONV_DIM  2304           // D_INNER + 2*D_STATE
#define D_IN_PROJ 4384           // 2*D_INNER + 2*D_STATE + NHEADS
#define BATCH     4
#define SEQ       2048
#define ROWS      (BATCH*SEQ)    // 8192
#define EPSV      1e-5f

#define NCHUNK    16
#define LCH       128
#define NBH       (BATCH*NHEADS) // 128
#define STATE_SZ  (HEADDIM*D_STATE)  // 8192

#define PR  132                  // padded 128-float row
#define PX  68                   // padded 64-float row

typedef unsigned long long ull;

// ---------------- Scratch ----------------
__device__ float g_zxb[(size_t)ROWS * D_IN_PROJ];
__device__ float g_xbc[(size_t)ROWS * CONV_DIM];
__device__ float g_dt [NBH*SEQ];
__device__ float g_la [NBH*SEQ];                    // A*dt (log dA)
__device__ float g_yb [(size_t)ROWS * D_INNER];

__device__ float g_st  [(size_t)NBH * NCHUNK * STATE_SZ];
__device__ float g_hini[(size_t)NBH * NCHUNK * STATE_SZ];
__device__ float g_cum [NBH * NCHUNK];

__device__ __nv_bfloat16 g_qh [(size_t)ROWS * D_MODEL];
__device__ __nv_bfloat16 g_ql [(size_t)ROWS * D_MODEL];
__device__ __nv_bfloat16 g_w1h[(size_t)D_IN_PROJ * D_MODEL];
__device__ __nv_bfloat16 g_w1l[(size_t)D_IN_PROJ * D_MODEL];
__device__ __nv_bfloat16 g_ynh[(size_t)ROWS * D_INNER];
__device__ __nv_bfloat16 g_ynl[(size_t)ROWS * D_INNER];
__device__ __nv_bfloat16 g_w2h[(size_t)D_MODEL * D_INNER];
__device__ __nv_bfloat16 g_w2l[(size_t)D_MODEL * D_INNER];

// ---------------- f32x2 packed helpers ----------------
__device__ __forceinline__ ull pack2(float lo, float hi) {
    ull r; asm("mov.b64 %0, {%1,%2};" : "=l"(r) : "f"(lo), "f"(hi)); return r;
}
__device__ __forceinline__ void unpack2(ull v, float& lo, float& hi) {
    asm("mov.b64 {%0,%1}, %2;" : "=f"(lo), "=f"(hi) : "l"(v));
}
__device__ __forceinline__ void fma2(ull& d, ull a, ull b) {
    asm("fma.rn.f32x2 %0, %1, %2, %0;" : "+l"(d) : "l"(a), "l"(b));
}
__device__ __forceinline__ ull mul2(ull a, ull b) {
    ull r; asm("mul.rn.f32x2 %0, %1, %2;" : "=l"(r) : "l"(a), "l"(b)); return r;
}
#define COMP(v,k) ((k)==0?(v).x:((k)==1?(v).y:((k)==2?(v).z:(v).w)))

// ---------------- cp.async helpers ----------------
__device__ __forceinline__ void cp16(unsigned s, const void* g) {
    asm volatile("cp.async.ca.shared.global [%0], [%1], 16;" :: "r"(s), "l"(g));
}
__device__ __forceinline__ void cp16z(unsigned s, const void* g, unsigned sz) {
    asm volatile("cp.async.ca.shared.global [%0], [%1], 16, %2;" :: "r"(s), "l"(g), "r"(sz));
}
__device__ __forceinline__ void cp_commit() { asm volatile("cp.async.commit_group;"); }
template<int N> __device__ __forceinline__ void cp_wait() {
    asm volatile("cp.async.wait_group %0;" :: "n"(N));
}
__device__ __forceinline__ unsigned smem_u32(const void* p) {
    return (unsigned)__cvta_generic_to_shared(p);
}

// ---------------- mma.sync + ldmatrix ----------------
#define LDSM4(r, addr) \
    asm volatile("ldmatrix.sync.aligned.m8n8.x4.shared.b16 {%0,%1,%2,%3}, [%4];" \
        : "=r"((r)[0]), "=r"((r)[1]), "=r"((r)[2]), "=r"((r)[3]) : "r"(addr))

#define MMA16816(d, a, b) \
    asm volatile("mma.sync.aligned.m16n8k16.row.col.f32.bf16.bf16.f32 " \
        "{%0,%1,%2,%3}, {%4,%5,%6,%7}, {%8,%9}, {%0,%1,%2,%3};" \
        : "+f"((d)[0]), "+f"((d)[1]), "+f"((d)[2]), "+f"((d)[3]) \
        : "r"((a)[0]), "r"((a)[1]), "r"((a)[2]), "r"((a)[3]), \
          "r"((b)[0]), "r"((b)[1]))

// =====================================================================
// Split-bf16 HMMA GEMM (NT): C = Ah*Bh + Al*Bh + Ah*Bl   (unchanged)
// =====================================================================
#define GEMM_STG   98304
#define GEMM_SMEM  (2*GEMM_STG)

__global__ void __launch_bounds__(256, 1)
gemm_mma(const __nv_bfloat16* __restrict__ A_h, const __nv_bfloat16* __restrict__ A_l,
         const __nv_bfloat16* __restrict__ B_h, const __nv_bfloat16* __restrict__ B_l,
         float* __restrict__ C, int M, int N, int K)
{
    extern __shared__ __align__(1024) char sm[];
    const unsigned base = smem_u32(sm);
    const int tid  = threadIdx.x;
    const int lane = tid & 31;
    const int wid  = tid >> 5;
    const int wm   = wid >> 2;
    const int wn   = wid & 3;
    const int m0   = blockIdx.y * 128;
    const int n0   = blockIdx.x * 256;

    float acc[4][8][4];
#pragma unroll
    for (int t = 0; t < 4; t++)
#pragma unroll
        for (int u = 0; u < 8; u++)
#pragma unroll
            for (int v = 0; v < 4; v++) acc[t][u][v] = 0.f;

    auto load_stage = [&](int s, unsigned stg) {
        const int k0 = s * 64;
#pragma unroll
        for (int i = 0; i < 4; i++) {
            const int ch = tid + i * 256;
            const int row = ch >> 3, c = ch & 7;
            const unsigned off = (unsigned)(row * 128) + ((unsigned)(c ^ (row & 7)) << 4);
            const size_t g = (size_t)(m0 + row) * K + k0 + c * 8;
            cp16(stg + off,         A_h + g);
            cp16(stg + 16384 + off, A_l + g);
        }
#pragma unroll
        for (int i = 0; i < 8; i++) {
            const int ch = tid + i * 256;
            const int row = ch >> 3, c = ch & 7;
            const unsigned off = (unsigned)(row * 128) + ((unsigned)(c ^ (row & 7)) << 4);
            const int gr = n0 + row;
            const unsigned sz = (gr < N) ? 16u : 0u;
            const int grc = (gr < N) ? gr : 0;
            const size_t g = (size_t)grc * K + k0 + c * 8;
            cp16z(stg + 32768 + off, B_h + g, sz);
            cp16z(stg + 65536 + off, B_l + g, sz);
        }
        cp_commit();
    };

    const int S = K / 64;
    load_stage(0, base);

    for (int s = 0; s < S; s++) {
        const unsigned stg = base + (unsigned)(s & 1) * GEMM_STG;
        if (s + 1 < S) {
            load_stage(s + 1, base + (unsigned)((s + 1) & 1) * GEMM_STG);
            cp_wait<1>();
        } else {
            cp_wait<0>();
        }
        __syncthreads();

        const unsigned stgA  = stg;
        const unsigned stgAl = stg + 16384;
        const unsigned stgB  = stg + 32768;
        const unsigned stgBl = stg + 65536;

#pragma unroll
        for (int ks = 0; ks < 4; ks++) {
            unsigned ah[4][4], al[4][4], bb[8][2];
            const unsigned akoff = ((unsigned)((ks * 2 + (lane >> 4)) ^ (lane & 7))) << 4;
#pragma unroll
            for (int t = 0; t < 4; t++) {
                const unsigned ro = (unsigned)((wm * 64 + t * 16 + (lane & 15)) * 128);
                LDSM4(ah[t], stgA  + ro + akoff);
                LDSM4(al[t], stgAl + ro + akoff);
            }
            const unsigned bkoff = ((unsigned)((ks * 2 + ((lane >> 3) & 1)) ^ (lane & 7))) << 4;
#pragma unroll
            for (int p = 0; p < 4; p++) {
                const unsigned ro = (unsigned)((wn * 64 + p * 16 + (lane & 7) + ((lane & 16) >> 1)) * 128);
                unsigned r[4];
                LDSM4(r, stgB + ro + bkoff);
                bb[2*p][0] = r[0]; bb[2*p][1] = r[1];
                bb[2*p+1][0] = r[2]; bb[2*p+1][1] = r[3];
            }
#pragma unroll
            for (int t = 0; t < 4; t++)
#pragma unroll
                for (int u = 0; u < 8; u++) {
                    MMA16816(acc[t][u], ah[t], bb[u]);
                    MMA16816(acc[t][u], al[t], bb[u]);
                }
#pragma unroll
            for (int p = 0; p < 4; p++) {
                const unsigned ro = (unsigned)((wn * 64 + p * 16 + (lane & 7) + ((lane & 16) >> 1)) * 128);
                unsigned r[4];
                LDSM4(r, stgBl + ro + bkoff);
                bb[2*p][0] = r[0]; bb[2*p][1] = r[1];
                bb[2*p+1][0] = r[2]; bb[2*p+1][1] = r[3];
            }
#pragma unroll
            for (int t = 0; t < 4; t++)
#pragma unroll
                for (int u = 0; u < 8; u++)
                    MMA16816(acc[t][u], ah[t], bb[u]);
        }
        __syncthreads();
    }

#pragma unroll
    for (int t = 0; t < 4; t++) {
        const int row = m0 + wm * 64 + t * 16 + (lane >> 2);
#pragma unroll
        for (int u = 0; u < 8; u++) {
            const int col = n0 + wn * 64 + u * 8 + (lane & 3) * 2;
            if (col < N) {
                *(float2*)(C + (size_t)row * N + col)       = make_float2(acc[t][u][0], acc[t][u][1]);
                *(float2*)(C + (size_t)(row + 8) * N + col) = make_float2(acc[t][u][2], acc[t][u][3]);
            }
        }
    }
}

// =====================================================================
// fp32 -> (bf16 hi, bf16 lo) split conversion
// =====================================================================
__global__ void __launch_bounds__(256) cvt_pair(const float* __restrict__ src,
                                                __nv_bfloat16* __restrict__ h,
                                                __nv_bfloat16* __restrict__ l, int n4)
{
    const int i = blockIdx.x * 256 + threadIdx.x;
    if (i >= n4) return;
    const float4 v = ((const float4*)src)[i];
    __nv_bfloat16 h0 = __float2bfloat16(v.x), h1 = __float2bfloat16(v.y),
                  h2 = __float2bfloat16(v.z), h3 = __float2bfloat16(v.w);
    __nv_bfloat16 l0 = __float2bfloat16(v.x - __bfloat162float(h0));
    __nv_bfloat16 l1 = __float2bfloat16(v.y - __bfloat162float(h1));
    __nv_bfloat16 l2 = __float2bfloat16(v.z - __bfloat162float(h2));
    __nv_bfloat16 l3 = __float2bfloat16(v.w - __bfloat162float(h3));
    ushort4 hv = make_ushort4(*(unsigned short*)&h0, *(unsigned short*)&h1,
                              *(unsigned short*)&h2, *(unsigned short*)&h3);
    ushort4 lv = make_ushort4(*(unsigned short*)&l0, *(unsigned short*)&l1,
                              *(unsigned short*)&l2, *(unsigned short*)&l3);
    ((ushort4*)h)[i] = hv;
    ((ushort4*)l)[i] = lv;
}

// =====================================================================
// Depthwise causal conv (width 4) + SiLU
// =====================================================================
__global__ void __launch_bounds__(256) conv_silu_kernel(const float* __restrict__ conv_w,
                                                        const float* __restrict__ conv_b)
{
    const int c  = blockIdx.x * 256 + threadIdx.x;
    const int l0 = blockIdx.y * 128;
    const int b  = blockIdx.z;

    const float w0 = conv_w[c*4+0], w1 = conv_w[c*4+1],
                w2 = conv_w[c*4+2], w3 = conv_w[c*4+3];
    const float bias = conv_b[c];

    const float* src = g_zxb + (size_t)(b*SEQ) * D_IN_PROJ + D_INNER + c;
    float*       dst = g_xbc + (size_t)(b*SEQ) * CONV_DIM + c;

    float xm3 = (l0-3 >= 0) ? src[(size_t)(l0-3) * D_IN_PROJ] : 0.f;
    float xm2 = (l0-2 >= 0) ? src[(size_t)(l0-2) * D_IN_PROJ] : 0.f;
    float xm1 = (l0-1 >= 0) ? src[(size_t)(l0-1) * D_IN_PROJ] : 0.f;

    for (int l = l0; l < l0 + 128; l++) {
        const float xc = src[(size_t)l * D_IN_PROJ];
        float v = bias + w0*xm3 + w1*xm2 + w2*xm1 + w3*xc;
        v = v / (1.f + expf(-v));
        dst[(size_t)l * CONV_DIM] = v;
        xm3 = xm2; xm2 = xm1; xm1 = xc;
    }
}

// =====================================================================
// dt = softplus(raw + dt_bias); la = A*dt   layout [bh][l]
// =====================================================================
__global__ void __launch_bounds__(256) dt_kernel(const float* __restrict__ dt_bias,
                                                 const float* __restrict__ A_log)
{
    const int idx = blockIdx.x * 256 + threadIdx.x;
    if (idx >= NBH*SEQ) return;
    const int l = idx & (SEQ-1);
    const int h = (idx >> 11) & (NHEADS-1);
    const int b = idx >> 16;
    const float raw = g_zxb[(size_t)(b*SEQ + l) * D_IN_PROJ + (D_IN_PROJ - NHEADS) + h]
                      + dt_bias[h];
    const float sp = (raw > 20.f) ? raw : log1pf(expf(raw));
    const float Ahv = -expf(A_log[h]);
    g_dt[idx] = sp;
    g_la[idx] = Ahv * sp;
}

// =====================================================================
// SSD phase 1: per-chunk final local state via outer-product GEMM.
// S[p,n] = sum_s exp(cs_L - cs_s) * dt_s * x_s[p] * B_s[n]
// grid (NCHUNK, NBH), 256 threads. thread: pg=tid>>4 (p-quad), ng=tid&15 (n-octet)
// =====================================================================
#define SSDA_SMEM ((128*PR + 128*PX + 384) * 4)

__global__ void __launch_bounds__(256, 2) ssd_state_kernel()
{
    extern __shared__ float sma[];
    float* sB  = sma;                 // [128][PR]
    float* sVW = sB + 128*PR;         // [128][PX]  dt*w*x
    float* sCS = sVW + 128*PX;        // [128]
    float* sDT = sCS + 128;           // [128]
    float* sLA = sDT + 128;           // [128]

    const int ck = blockIdx.x, bh = blockIdx.y;
    const int b  = bh >> 5, hh = bh & 31;
    const int tid = threadIdx.x;
    const size_t rbase = (size_t)(b*SEQ + ck*LCH);

#pragma unroll
    for (int i = 0; i < 16; i++) {
        int idx = i*256 + tid; int t = idx >> 5, f4 = idx & 31;
        cp16(smem_u32(sB + t*PR + f4*4),
             g_xbc + (rbase + t)*CONV_DIM + D_INNER + f4*4);
    }
#pragma unroll
    for (int i = 0; i < 8; i++) {
        int idx = i*256 + tid; int t = idx >> 4, f4 = idx & 15;
        cp16(smem_u32(sVW + t*PX + f4*4),
             g_xbc + (rbase + t)*CONV_DIM + hh*HEADDIM + f4*4);
    }
    if (tid < 128) {
        sDT[tid] = g_dt[(size_t)bh*SEQ + ck*LCH + tid];
        sLA[tid] = g_la[(size_t)bh*SEQ + ck*LCH + tid];
    }
    cp_commit(); cp_wait<0>();
    __syncthreads();
    if (tid == 0) {
        float c = 0.f;
        for (int s = 0; s < 128; s++) { c += sLA[s]; sCS[s] = c; }
    }
    __syncthreads();
    const float csL = sCS[127];
    if (tid < 128) {
        const float w = __expf(csL - sCS[tid]) * sDT[tid];
        float* row = sVW + tid*PX;
#pragma unroll
        for (int p = 0; p < 64; p += 4) {
            float4 v = *(float4*)(row + p);
            v.x *= w; v.y *= w; v.z *= w; v.w *= w;
            *(float4*)(row + p) = v;
        }
    }
    if (tid == 0) g_cum[bh*NCHUNK + ck] = __expf(csL);
    __syncthreads();

    const int pg = tid >> 4;   // p = pg*4 + i
    const int ng = tid & 15;   // n = ng*8 + ...

    ull Sp[4][4];
#pragma unroll
    for (int i = 0; i < 4; i++)
#pragma unroll
        for (int q = 0; q < 4; q++) Sp[i][q] = 0ull;

#pragma unroll 4
    for (int s = 0; s < 128; s++) {
        const float4 v4  = *(const float4*)(sVW + s*PX + pg*4);
        const float4 b40 = *(const float4*)(sB + s*PR + ng*8);
        const float4 b41 = *(const float4*)(sB + s*PR + ng*8 + 4);
        ull bp[4] = { pack2(b40.x, b40.y), pack2(b40.z, b40.w),
                      pack2(b41.x, b41.y), pack2(b41.z, b41.w) };
#pragma unroll
        for (int i = 0; i < 4; i++) {
            const float vv = COMP(v4, i);
            const ull vc = pack2(vv, vv);
#pragma unroll
            for (int q = 0; q < 4; q++) fma2(Sp[i][q], vc, bp[q]);
        }
    }

    float* dst = g_st + (size_t)(bh*NCHUNK + ck)*STATE_SZ;
#pragma unroll
    for (int i = 0; i < 4; i++) {
        const int p = pg*4 + i;
        float o[8];
#pragma unroll
        for (int q = 0; q < 4; q++) unpack2(Sp[i][q], o[q*2], o[q*2+1]);
        *(float4*)(dst + p*D_STATE + ng*8)     = make_float4(o[0], o[1], o[2], o[3]);
        *(float4*)(dst + p*D_STATE + ng*8 + 4) = make_float4(o[4], o[5], o[6], o[7]);
    }
}

// =====================================================================
// SSD phase 2: combine across chunks.  grid NBH, 256 threads.
// =====================================================================
__global__ void __launch_bounds__(256) chunk_combine_kernel()
{
    const int bh  = blockIdx.x;
    const int tid = threadIdx.x;
    const size_t off = tid * 32;

    float4 h[8];
#pragma unroll
    for (int i = 0; i < 8; i++) h[i] = make_float4(0.f, 0.f, 0.f, 0.f);

    for (int ck = 0; ck < NCHUNK; ck++) {
        float4* hi = (float4*)(g_hini + (size_t)(bh * NCHUNK + ck) * STATE_SZ + off);
#pragma unroll
        for (int i = 0; i < 8; i++) hi[i] = h[i];
        if (ck < NCHUNK - 1) {
            const float a = g_cum[bh * NCHUNK + ck];
            const float4* s = (const float4*)(g_st + (size_t)(bh * NCHUNK + ck) * STATE_SZ + off);
#pragma unroll
            for (int i = 0; i < 8; i++) {
                float4 sv = s[i];
                h[i].x = a * h[i].x + sv.x;
                h[i].y = a * h[i].y + sv.y;
                h[i].z = a * h[i].z + sv.z;
                h[i].w = a * h[i].w + sv.w;
            }
        }
    }
}

// =====================================================================
// SSD phase 3: per-chunk outputs via GEMMs.
//   G[t,s] = C_t.B_s ; M = tril(exp(cs_t-cs_s)*dt_s*G) ;
//   y = M.x + exp(cs_t)*(C.h_init^T) + D*x
// grid (NCHUNK, NBH), 256 threads: tt=tid>>4 (t-octet), tp=tid&15 (p=tp+16j)
// =====================================================================
#define SSDO_SMEM ((2*128*PR + 128*PX + 64*PR + 384) * 4)

__global__ void __launch_bounds__(256, 1) ssd_out_kernel(const float* __restrict__ Dvec)
{
    extern __shared__ float smo[];
    float* sC  = smo;                  // [128][PR]  (reused as sXT [64][PR])
    float* sB  = sC + 128*PR;          // [128][PR]  (reused as M)
    float* sX  = sB + 128*PR;          // [128][PX]
    float* sH  = sX + 128*PX;          // [64][PR]
    float* sCS = sH + 64*PR;           // [128]
    float* sDT = sCS + 128;            // [128]
    float* sLA = sDT + 128;            // [128]
    float* sXT = sC;

    const int ck = blockIdx.x, bh = blockIdx.y;
    const int b  = bh >> 5, hh = bh & 31;
    const int tid = threadIdx.x;
    const size_t rbase = (size_t)(b*SEQ + ck*LCH);

#pragma unroll
    for (int i = 0; i < 16; i++) {
        int idx = i*256 + tid; int t = idx >> 5, f4 = idx & 31;
        const float* row = g_xbc + (rbase + t)*CONV_DIM;
        cp16(smem_u32(sC + t*PR + f4*4), row + D_INNER + D_STATE + f4*4);
        cp16(smem_u32(sB + t*PR + f4*4), row + D_INNER + f4*4);
    }
#pragma unroll
    for (int i = 0; i < 8; i++) {
        int idx = i*256 + tid; int t = idx >> 4, f4 = idx & 15;
        cp16(smem_u32(sX + t*PX + f4*4),
             g_xbc + (rbase + t)*CONV_DIM + hh*HEADDIM + f4*4);
    }
    {
        const float* hsrc = g_hini + (size_t)(bh*NCHUNK + ck)*STATE_SZ;
#pragma unroll
        for (int i = 0; i < 8; i++) {
            int idx = i*256 + tid; int p = idx >> 5, f4 = idx & 31;
            cp16(smem_u32(sH + p*PR + f4*4), hsrc + p*D_STATE + f4*4);
        }
    }
    if (tid < 128) {
        sDT[tid] = g_dt[(size_t)bh*SEQ + ck*LCH + tid];
        sLA[tid] = g_la[(size_t)bh*SEQ + ck*LCH + tid];
    }
    cp_commit(); cp_wait<0>();
    __syncthreads();
    if (tid == 0) {
        float c = 0.f;
        for (int s = 0; s < 128; s++) { c += sLA[s]; sCS[s] = c; }
    }
    __syncthreads();

    const int tt = tid >> 4;   // t = tt*8 + i
    const int tp = tid & 15;   // p = tp + 16*j

    ull Yp[8][2];              // lanes: (j,j+1) pairs: [0]=(j0,j1), [1]=(j2,j3)
#pragma unroll
    for (int i = 0; i < 8; i++) { Yp[i][0] = 0ull; Yp[i][1] = 0ull; }
    ull Gp[8][4];              // lanes: (m=2q, m=2q+1), s = tp + 16*m
#pragma unroll
    for (int i = 0; i < 8; i++)
#pragma unroll
        for (int q = 0; q < 4; q++) Gp[i][q] = 0ull;

    // ---- fused n-loop: Y2 (C.h_init) and G (C.B^T) ----
    for (int n4 = 0; n4 < 32; n4++) {
        float4 c4[8], h4[4], b4[8];
#pragma unroll
        for (int i = 0; i < 8; i++) c4[i] = *(const float4*)(sC + (tt*8+i)*PR + n4*4);
#pragma unroll
        for (int j = 0; j < 4; j++) h4[j] = *(const float4*)(sH + (tp+16*j)*PR + n4*4);
#pragma unroll
        for (int m = 0; m < 8; m++) b4[m] = *(const float4*)(sB + (tp+16*m)*PR + n4*4);
#pragma unroll
        for (int k = 0; k < 4; k++) {
            ull hq[2] = { pack2(COMP(h4[0],k), COMP(h4[1],k)),
                          pack2(COMP(h4[2],k), COMP(h4[3],k)) };
            ull bq[4];
#pragma unroll
            for (int q = 0; q < 4; q++)
                bq[q] = pack2(COMP(b4[2*q],k), COMP(b4[2*q+1],k));
#pragma unroll
            for (int i = 0; i < 8; i++) {
                const float cv = COMP(c4[i], k);
                const ull cc = pack2(cv, cv);
                fma2(Yp[i][0], cc, hq[0]);
                fma2(Yp[i][1], cc, hq[1]);
#pragma unroll
                for (int q = 0; q < 4; q++) fma2(Gp[i][q], cc, bq[q]);
            }
        }
    }

    // scale Y2 by exp(cs_t)
#pragma unroll
    for (int i = 0; i < 8; i++) {
        const float w = __expf(sCS[tt*8 + i]);
        const ull ww = pack2(w, w);
        Yp[i][0] = mul2(Yp[i][0], ww);
        Yp[i][1] = mul2(Yp[i][1], ww);
    }

    __syncthreads();   // done reading sC / sB / sH

    // ---- mask + weight G -> M (into sB); transpose x -> sXT (into sC) ----
#pragma unroll
    for (int i = 0; i < 8; i++) {
        const int t = tt*8 + i;
        const float et = sCS[t];
#pragma unroll
        for (int q = 0; q < 4; q++) {
            float g0, g1; unpack2(Gp[i][q], g0, g1);
            const int s0 = tp + 16*(2*q);
            const int s1 = tp + 16*(2*q + 1);
            sB[t*PR + s0] = (s0 <= t) ? g0 * __expf(et - sCS[s0]) * sDT[s0] : 0.f;
            sB[t*PR + s1] = (s1 <= t) ? g1 * __expf(et - sCS[s1]) * sDT[s1] : 0.f;
        }
    }
#pragma unroll
    for (int i = 0; i < 32; i++) {
        int e = i*256 + tid; int s = e >> 6, p = e & 63;
        sXT[p*PR + s] = sX[s*PX + p];
    }
    __syncthreads();

    // ---- Y1: y += M . x  over s ----
    for (int s4 = 0; s4 < 32; s4++) {
        float4 m4[8], x4[4];
#pragma unroll
        for (int i = 0; i < 8; i++) m4[i] = *(const float4*)(sB + (tt*8+i)*PR + s4*4);
#pragma unroll
        for (int j = 0; j < 4; j++) x4[j] = *(const float4*)(sXT + (tp+16*j)*PR + s4*4);
#pragma unroll
        for (int k = 0; k < 4; k++) {
            ull xq[2] = { pack2(COMP(x4[0],k), COMP(x4[1],k)),
                          pack2(COMP(x4[2],k), COMP(x4[3],k)) };
#pragma unroll
            for (int i = 0; i < 8; i++) {
                const float mv = COMP(m4[i], k);
                const ull mm = pack2(mv, mv);
                fma2(Yp[i][0], mm, xq[0]);
                fma2(Yp[i][1], mm, xq[1]);
            }
        }
    }

    // ---- epilogue: + D*x, write y ----
    const float Dv = Dvec[hh];
#pragma unroll
    for (int i = 0; i < 8; i++) {
        const int t = tt*8 + i;
        float* orow = g_yb + ((rbase + t) * NHEADS + hh) * HEADDIM;
        float y0, y1, y2, y3;
        unpack2(Yp[i][0], y0, y1);
        unpack2(Yp[i][1], y2, y3);
        orow[tp]      = y0 + Dv * sX[t*PX + tp];
        orow[tp + 16] = y1 + Dv * sX[t*PX + tp + 16];
        orow[tp + 32] = y2 + Dv * sX[t*PX + tp + 32];
        orow[tp + 48] = y3 + Dv * sX[t*PX + tp + 48];
    }
}

// =====================================================================
// y = yb * silu(z); rmsnorm; write bf16 hi/lo split
// =====================================================================
__global__ void __launch_bounds__(256) gate_norm_kernel(const float* __restrict__ norm_w)
{
    const int row = blockIdx.x;
    const int tid = threadIdx.x;
    const float* yb = g_yb + (size_t)row * D_INNER;
    const float* zr = g_zxb + (size_t)row * D_IN_PROJ;

    float v[8];
    float ss = 0.f;
#pragma unroll
    for (int j = 0; j < 8; j++) {
        const int idx = tid + j*256;
        const float z = zr[idx];
        const float sg = z / (1.f + expf(-z));
        const float val = yb[idx] * sg;
        v[j] = val;
        ss += val * val;
    }
#pragma unroll
    for (int o = 16; o > 0; o >>= 1) ss += __shfl_xor_sync(0xffffffffu, ss, o);

    __shared__ float red[8];
    __shared__ float sscale;
    if ((tid & 31) == 0) red[tid >> 5] = ss;
    __syncthreads();
    if (tid == 0) {
        float tot = 0.f;
#pragma unroll
        for (int i = 0; i < 8; i++) tot += red[i];
        sscale = rsqrtf(tot / (float)D_INNER + EPSV);
    }
    __syncthreads();
    const float scale = sscale;

    __nv_bfloat16* oh = g_ynh + (size_t)row * D_INNER;
    __nv_bfloat16* ol = g_ynl + (size_t)row * D_INNER;
#pragma unroll
    for (int j = 0; j < 8; j++) {
        const int idx = tid + j*256;
        const float y = v[j] * scale * norm_w[idx];
        const __nv_bfloat16 hi = __float2bfloat16(y);
        oh[idx] = hi;
        ol[idx] = __float2bfloat16(y - __bfloat162float(hi));
    }
}

// =====================================================================
// Launch
// inputs: 0 query, 1 key, 2 value, 3 in_proj_w, 4 conv_w, 5 conv_b,
//         6 dt_bias, 7 A_log, 8 D, 9 norm_w, 10 out_proj_w
// =====================================================================
extern "C" void kernel_launch(void* const* d_in, const int* in_sizes, int n_in,
                              void* d_out, int out_size)
{
    const float* q          = (const float*)d_in[0];
    const float* in_proj_w  = (const float*)d_in[3];
    const float* conv_w     = (const float*)d_in[4];
    const float* conv_b     = (const float*)d_in[5];
    const float* dt_bias    = (const float*)d_in[6];
    const float* A_log      = (const float*)d_in[7];
    const float* Dvec       = (const float*)d_in[8];
    const float* norm_w     = (const float*)d_in[9];
    const float* out_proj_w = (const float*)d_in[10];
    float* out              = (float*)d_out;

    float* zxb; cudaGetSymbolAddress((void**)&zxb, g_zxb);
    __nv_bfloat16 *qh, *ql, *w1h, *w1l, *ynh, *ynl, *w2h, *w2l;
    cudaGetSymbolAddress((void**)&qh,  g_qh);
    cudaGetSymbolAddress((void**)&ql,  g_ql);
    cudaGetSymbolAddress((void**)&w1h, g_w1h);
    cudaGetSymbolAddress((void**)&w1l, g_w1l);
    cudaGetSymbolAddress((void**)&ynh, g_ynh);
    cudaGetSymbolAddress((void**)&ynl, g_ynl);
    cudaGetSymbolAddress((void**)&w2h, g_w2h);
    cudaGetSymbolAddress((void**)&w2l, g_w2l);

    cudaFuncSetAttribute(gemm_mma, cudaFuncAttributeMaxDynamicSharedMemorySize, GEMM_SMEM);
    cudaFuncSetAttribute(ssd_state_kernel, cudaFuncAttributeMaxDynamicSharedMemorySize, SSDA_SMEM);
    cudaFuncSetAttribute(ssd_out_kernel, cudaFuncAttributeMaxDynamicSharedMemorySize, SSDO_SMEM);

    // 0) split-convert GEMM operands
    {
        const int nq = ROWS * D_MODEL / 4;
        cvt_pair<<<(nq + 255)/256, 256>>>(q, qh, ql, nq);
        const int nw1 = D_IN_PROJ * D_MODEL / 4;
        cvt_pair<<<(nw1 + 255)/256, 256>>>(in_proj_w, w1h, w1l, nw1);
        const int nw2 = D_MODEL * D_INNER / 4;
        cvt_pair<<<(nw2 + 255)/256, 256>>>(out_proj_w, w2h, w2l, nw2);
    }

    // 1) zxbcdt = q @ in_proj_w^T
    gemm_mma<<<dim3((D_IN_PROJ + 255)/256, ROWS/128), 256, GEMM_SMEM>>>(
        qh, ql, w1h, w1l, zxb, ROWS, D_IN_PROJ, D_MODEL);

    // 2) causal conv4 + SiLU
    conv_silu_kernel<<<dim3(CONV_DIM/256, SEQ/128, BATCH), 256>>>(conv_w, conv_b);

    // 3) dt / la
    dt_kernel<<<(NBH*SEQ + 255)/256, 256>>>(dt_bias, A_log);

    // 4) SSD chunked scan (GEMM-formulated, 3 phases)
    ssd_state_kernel<<<dim3(NCHUNK, NBH), 256, SSDA_SMEM>>>();
    chunk_combine_kernel<<<NBH, 256>>>();
    ssd_out_kernel<<<dim3(NCHUNK, NBH), 256, SSDO_SMEM>>>(Dvec);

    // 5) gate + RMSNorm (emits bf16 hi/lo)
    gate_norm_kernel<<<ROWS, 256>>>(norm_w);

    // 6) out = yn @ out_proj_w^T
    gemm_mma<<<dim3(D_MODEL/256, ROWS/128), 256, GEMM_SMEM>>>(
        ynh, ynl, w2h, w2l, out, ROWS, D_MODEL, D_INNER);
}